// round 1
// baseline (speedup 1.0000x reference)
#include <cuda_runtime.h>
#include <cuda_bf16.h>
#include <math.h>

#define H_DIM 1000
#define W_DIM 1000
#define NVERT 20
#define NPIX_THREAD 4
#define GROUPS_PER_ROW (W_DIM / NPIX_THREAD)          // 250
#define TOTAL_THREADS (H_DIM * GROUPS_PER_ROW)        // 250000
#define BLOCK 256

// Per-vertex precomputed params, padded to 32B (two float4 per vertex).
// [xn, yn, r2, E, cr, cg, cb, pad]
__device__ float g_vp[NVERT * 8];

__global__ void prepass_kernel(const float* __restrict__ vpos,
                               const float* __restrict__ vcol,
                               const float* __restrict__ vrad,
                               const float* __restrict__ cpos,
                               const float* __restrict__ crot,
                               const float* __restrict__ fl)
{
    int i = threadIdx.x;
    if (i >= NVERT) return;
    float px = vpos[3*i+0], py = vpos[3*i+1], pz = vpos[3*i+2];
    // p_cam = vert_pos @ cam_rot + cam_pos  (row-vector * row-major 3x3)
    float x = px*crot[0] + py*crot[3] + pz*crot[6] + cpos[0];
    float y = px*crot[1] + py*crot[4] + pz*crot[7] + cpos[1];
    float z = px*crot[2] + py*crot[5] + pz*crot[8] + cpos[2];
    float f = fl[0];
    float xn = f * x / z;
    float yn = f * y / z;
    float rn = f * vrad[i] / z;
    bool in_depth = (z > 1.0f) && (z < 45.0f);
    float closeness = fminf(fmaxf((45.0f - z) * (1.0f / 44.0f), 0.0f), 1.0f);
    // logit = closeness / GAMMA = closeness * 10; weight = exp(logit) (bg logit = 0)
    float E = in_depth ? expf(closeness * 10.0f) : 0.0f;
    float* p = g_vp + i * 8;
    p[0] = xn; p[1] = yn; p[2] = rn * rn; p[3] = E;
    p[4] = vcol[3*i+0]; p[5] = vcol[3*i+1]; p[6] = vcol[3*i+2]; p[7] = 0.0f;
}

__global__ void __launch_bounds__(BLOCK)
render_kernel(const float* __restrict__ bg, float* __restrict__ out)
{
    __shared__ float4 sp[NVERT * 2];
    int t = threadIdx.x;
    if (t < NVERT * 2) sp[t] = reinterpret_cast<const float4*>(g_vp)[t];
    __syncthreads();

    int idx = blockIdx.x * BLOCK + t;
    if (idx >= TOTAL_THREADS) return;

    int row = idx / GROUPS_PER_ROW;
    int xg  = idx - row * GROUPS_PER_ROW;
    int x0  = xg * NPIX_THREAD;

    const float gy  = 1.0f - (2.0f * row + 1.0f) * (1.0f / H_DIM);
    const float dgx = -2.0f / W_DIM;
    float gx0 = 1.0f - (2.0f * x0 + 1.0f) * (1.0f / W_DIM);
    float gx1 = gx0 + dgx;
    float gx2 = gx1 + dgx;
    float gx3 = gx2 + dgx;

    float bgr = bg[0], bgg = bg[1], bgb = bg[2];
    // Background: logit 0 -> exp = 1
    float s0 = 1.0f, s1 = 1.0f, s2 = 1.0f, s3 = 1.0f;
    float r0 = bgr, g0 = bgg, b0 = bgb;
    float r1 = bgr, g1 = bgg, b1 = bgb;
    float r2 = bgr, g2 = bgg, b2 = bgb;
    float r3 = bgr, g3 = bgg, b3 = bgb;

#pragma unroll
    for (int i = 0; i < NVERT; i++) {
        float4 a = sp[2*i];     // xn, yn, r2, E
        float4 c = sp[2*i+1];   // cr, cg, cb, pad
        float dy  = gy - a.y;
        float dy2 = dy * dy;

        float dx0 = gx0 - a.x;
        float d0  = fmaf(dx0, dx0, dy2);
        float w0  = (d0 <= a.z) ? a.w : 0.0f;
        s0 += w0;
        r0 = fmaf(w0, c.x, r0); g0 = fmaf(w0, c.y, g0); b0 = fmaf(w0, c.z, b0);

        float dx1 = gx1 - a.x;
        float d1  = fmaf(dx1, dx1, dy2);
        float w1  = (d1 <= a.z) ? a.w : 0.0f;
        s1 += w1;
        r1 = fmaf(w1, c.x, r1); g1 = fmaf(w1, c.y, g1); b1 = fmaf(w1, c.z, b1);

        float dx2 = gx2 - a.x;
        float d2  = fmaf(dx2, dx2, dy2);
        float w2  = (d2 <= a.z) ? a.w : 0.0f;
        s2 += w2;
        r2 = fmaf(w2, c.x, r2); g2 = fmaf(w2, c.y, g2); b2 = fmaf(w2, c.z, b2);

        float dx3 = gx3 - a.x;
        float d3  = fmaf(dx3, dx3, dy2);
        float w3  = (d3 <= a.z) ? a.w : 0.0f;
        s3 += w3;
        r3 = fmaf(w3, c.x, r3); g3 = fmaf(w3, c.y, g3); b3 = fmaf(w3, c.z, b3);
    }

    float i0 = __fdividef(1.0f, s0);
    float i1 = __fdividef(1.0f, s1);
    float i2 = __fdividef(1.0f, s2);
    float i3 = __fdividef(1.0f, s3);

    float4 o0 = make_float4(r0 * i0, g0 * i0, b0 * i0, r1 * i1);
    float4 o1 = make_float4(g1 * i1, b1 * i1, r2 * i2, g2 * i2);
    float4 o2 = make_float4(b2 * i2, r3 * i3, g3 * i3, b3 * i3);

    float4* out4 = reinterpret_cast<float4*>(out) + (size_t)idx * 3;
    out4[0] = o0;
    out4[1] = o1;
    out4[2] = o2;
}

extern "C" void kernel_launch(void* const* d_in, const int* in_sizes, int n_in,
                              void* d_out, int out_size)
{
    const float* vert_pos = (const float*)d_in[0];
    const float* vert_col = (const float*)d_in[1];
    const float* vert_rad = (const float*)d_in[2];
    const float* cam_pos  = (const float*)d_in[3];
    const float* cam_rot  = (const float*)d_in[4];
    const float* focal    = (const float*)d_in[5];
    const float* bg_col   = (const float*)d_in[6];
    float* out = (float*)d_out;

    prepass_kernel<<<1, 32>>>(vert_pos, vert_col, vert_rad, cam_pos, cam_rot, focal);
    int grid = (TOTAL_THREADS + BLOCK - 1) / BLOCK;   // 977
    render_kernel<<<grid, BLOCK>>>(bg_col, out);
}

// round 2
// speedup vs baseline: 1.4625x; 1.4625x over previous
#include <cuda_runtime.h>
#include <cuda_bf16.h>
#include <math.h>

#define H_DIM 1000
#define W_DIM 1000
#define NVERT 20
#define NPIX_THREAD 4
#define BLOCK 250                      // one image row per block: 250 threads * 4 px

// Single fused kernel: one block per image row.
// Threads 0..19 project their vertex (prepass folded in), write params to shared,
// and vote on whether the vertex's circle intersects this row. The uniform
// ballot mask drives a sparse loop -> ~2 vertices per row on average vs 20.
__global__ void __launch_bounds__(256)
render_kernel(const float* __restrict__ vpos,
              const float* __restrict__ vcol,
              const float* __restrict__ vrad,
              const float* __restrict__ cpos,
              const float* __restrict__ crot,
              const float* __restrict__ fl,
              const float* __restrict__ bg,
              float* __restrict__ out)
{
    __shared__ float4 sp[NVERT * 2];   // [xn, yn, r2, E], [E*cr, E*cg, E*cb, 0]
    __shared__ unsigned smask;

    const int t   = threadIdx.x;
    const int row = blockIdx.x;
    const float gy = 1.0f - (2.0f * row + 1.0f) * (1.0f / H_DIM);

    if (t < 32) {
        bool cover = false;
        if (t < NVERT) {
            float px = vpos[3*t+0], py = vpos[3*t+1], pz = vpos[3*t+2];
            // p_cam = vert_pos @ cam_rot + cam_pos (row-vector * row-major 3x3)
            float x = fmaf(px, crot[0], fmaf(py, crot[3], fmaf(pz, crot[6], cpos[0])));
            float y = fmaf(px, crot[1], fmaf(py, crot[4], fmaf(pz, crot[7], cpos[1])));
            float z = fmaf(px, crot[2], fmaf(py, crot[5], fmaf(pz, crot[8], cpos[2])));
            float f    = fl[0];
            float invz = __fdividef(1.0f, z);
            float xn = f * x * invz;
            float yn = f * y * invz;
            float rn = f * vrad[t] * invz;
            float r2 = rn * rn;
            bool in_depth = (z > 1.0f) && (z < 45.0f);
            float closeness = fminf(fmaxf((45.0f - z) * (1.0f / 44.0f), 0.0f), 1.0f);
            float E = in_depth ? expf(closeness * 10.0f) : 0.0f;   // bg logit = 0 -> exp = 1
            sp[2*t]   = make_float4(xn, yn, r2, E);
            sp[2*t+1] = make_float4(E * vcol[3*t+0], E * vcol[3*t+1], E * vcol[3*t+2], 0.0f);
            float dy = gy - yn;
            cover = (dy * dy <= r2) && (E > 0.0f);
        }
        unsigned m = __ballot_sync(0xffffffffu, cover);
        if (t == 0) smask = m;
    }
    __syncthreads();

    unsigned mask = smask;

    const int x0 = t * NPIX_THREAD;
    const float dgx = -2.0f / W_DIM;
    float gx0 = 1.0f - (2.0f * x0 + 1.0f) * (1.0f / W_DIM);
    float gx1 = gx0 + dgx;
    float gx2 = gx1 + dgx;
    float gx3 = gx2 + dgx;

    const float bgr = bg[0], bgg = bg[1], bgb = bg[2];
    float s0 = 1.0f, s1 = 1.0f, s2 = 1.0f, s3 = 1.0f;  // background weight e^0 = 1
    float r0 = bgr, g0 = bgg, b0 = bgb;
    float r1 = bgr, g1 = bgg, b1 = bgb;
    float r2_ = bgr, g2 = bgg, b2 = bgb;
    float r3 = bgr, g3 = bgg, b3 = bgb;

    while (mask) {
        int i = __ffs(mask) - 1;
        mask &= mask - 1;
        float4 a = sp[2*i];       // xn, yn, r2, E
        float4 c = sp[2*i+1];     // E*cr, E*cg, E*cb
        float dy  = gy - a.y;
        float dy2 = dy * dy;

        float dx0 = gx0 - a.x;
        float d0  = fmaf(dx0, dx0, dy2);
        if (d0 <= a.z) { s0 += a.w; r0 += c.x; g0 += c.y; b0 += c.z; }

        float dx1 = gx1 - a.x;
        float d1  = fmaf(dx1, dx1, dy2);
        if (d1 <= a.z) { s1 += a.w; r1 += c.x; g1 += c.y; b1 += c.z; }

        float dx2 = gx2 - a.x;
        float d2  = fmaf(dx2, dx2, dy2);
        if (d2 <= a.z) { s2 += a.w; r2_ += c.x; g2 += c.y; b2 += c.z; }

        float dx3 = gx3 - a.x;
        float d3  = fmaf(dx3, dx3, dy2);
        if (d3 <= a.z) { s3 += a.w; r3 += c.x; g3 += c.y; b3 += c.z; }
    }

    float i0 = __fdividef(1.0f, s0);
    float i1 = __fdividef(1.0f, s1);
    float i2 = __fdividef(1.0f, s2);
    float i3 = __fdividef(1.0f, s3);

    float4 o0 = make_float4(r0 * i0, g0 * i0, b0 * i0, r1 * i1);
    float4 o1 = make_float4(g1 * i1, b1 * i1, r2_ * i2, g2 * i2);
    float4 o2 = make_float4(b2 * i2, r3 * i3, g3 * i3, b3 * i3);

    float4* out4 = reinterpret_cast<float4*>(out) + ((size_t)row * BLOCK + t) * 3;
    out4[0] = o0;
    out4[1] = o1;
    out4[2] = o2;
}

extern "C" void kernel_launch(void* const* d_in, const int* in_sizes, int n_in,
                              void* d_out, int out_size)
{
    const float* vert_pos = (const float*)d_in[0];
    const float* vert_col = (const float*)d_in[1];
    const float* vert_rad = (const float*)d_in[2];
    const float* cam_pos  = (const float*)d_in[3];
    const float* cam_rot  = (const float*)d_in[4];
    const float* focal    = (const float*)d_in[5];
    const float* bg_col   = (const float*)d_in[6];
    float* out = (float*)d_out;

    render_kernel<<<H_DIM, BLOCK>>>(vert_pos, vert_col, vert_rad,
                                    cam_pos, cam_rot, focal, bg_col, out);
}